// round 2
// baseline (speedup 1.0000x reference)
#include <cuda_runtime.h>
#include <cuda_bf16.h>

// Problem constants
#define B_SZ 128
#define L_SZ 4096
#define C_SZ 384
#define SPLITS 8
#define CHUNK (L_SZ / SPLITS)   // 512
#define NTHREADS 256            // 8 warps
#define NWARPS 8

__device__ __align__(16) float g_partial[B_SZ * SPLITS * C_SZ]; // unnormalized sum of w*v
__device__ float g_m[B_SZ * SPLITS];              // split max logit
__device__ float g_s[B_SZ * SPLITS];              // split sum exp

__global__ __launch_bounds__(NTHREADS) void attn_split_kernel(
    const float* __restrict__ q,
    const float* __restrict__ kc,
    const float* __restrict__ v)
{
    const int blk  = blockIdx.x;        // 0 .. B*SPLITS-1
    const int b    = blk / SPLITS;
    const int s    = blk % SPLITS;
    const int l0   = s * CHUNK;
    const int tid  = threadIdx.x;
    const int wid  = tid >> 5;
    const int lane = tid & 31;

    __shared__ __align__(16) float sh_q[C_SZ];
    __shared__ float sh_log[CHUNK];
    __shared__ float sh_red[NWARPS];
    __shared__ float sh_bmax;
    __shared__ __align__(16) float sh_acc[NWARPS][C_SZ]; // 12 KB

    // load q row into shared
    for (int i = tid; i < C_SZ; i += NTHREADS) sh_q[i] = q[b * C_SZ + i];
    __syncthreads();

    // each lane's 3 float4 fragments of q (covers 384 floats per warp)
    float4 qf[3];
#pragma unroll
    for (int j = 0; j < 3; j++)
        qf[j] = *reinterpret_cast<const float4*>(&sh_q[(lane + 32 * j) * 4]);

    const float inv_T = 1.0f / 19.595917942265423f;
    const size_t base = ((size_t)b * L_SZ + l0) * C_SZ;

    // ---- Pass 1: logits over this split's 512 rows (warp per row) ----
    float wmax = -1e30f;
    for (int l = wid; l < CHUNK; l += NWARPS) {
        const float4* krow = reinterpret_cast<const float4*>(kc + base + (size_t)l * C_SZ);
        float d = 0.f;
#pragma unroll
        for (int j = 0; j < 3; j++) {
            float4 k4 = krow[lane + 32 * j];
            d += qf[j].x * k4.x + qf[j].y * k4.y + qf[j].z * k4.z + qf[j].w * k4.w;
        }
#pragma unroll
        for (int o = 16; o; o >>= 1) d += __shfl_down_sync(0xffffffffu, d, o);
        d = __shfl_sync(0xffffffffu, d, 0);
        d *= inv_T;
        if (lane == 0) sh_log[l] = d;
        wmax = fmaxf(wmax, d);
    }
    if (lane == 0) sh_red[wid] = wmax;
    __syncthreads();
    if (tid == 0) {
        float m = sh_red[0];
#pragma unroll
        for (int i = 1; i < NWARPS; i++) m = fmaxf(m, sh_red[i]);
        sh_bmax = m;
    }
    __syncthreads();
    const float bmax = sh_bmax;

    // ---- softmax numerators + sum ----
    float psum = 0.f;
    for (int l = tid; l < CHUNK; l += NTHREADS) {
        float w = __expf(sh_log[l] - bmax);
        sh_log[l] = w;
        psum += w;
    }
#pragma unroll
    for (int o = 16; o; o >>= 1) psum += __shfl_down_sync(0xffffffffu, psum, o);
    if (lane == 0) sh_red[wid] = psum;
    __syncthreads();
    if (tid == 0) {
        float t = 0.f;
#pragma unroll
        for (int i = 0; i < NWARPS; i++) t += sh_red[i];
        g_m[blk] = bmax;
        g_s[blk] = t;
    }
    // sh_log fully written & visible after the __syncthreads above; pass 2 reads it
    __syncthreads();

    // ---- Pass 2: acc += w * v (warp per row) ----
    float4 acc0 = {0.f, 0.f, 0.f, 0.f};
    float4 acc1 = {0.f, 0.f, 0.f, 0.f};
    float4 acc2 = {0.f, 0.f, 0.f, 0.f};
    for (int l = wid; l < CHUNK; l += NWARPS) {
        const float w = sh_log[l];
        const float4* vrow = reinterpret_cast<const float4*>(v + base + (size_t)l * C_SZ);
        float4 v0 = vrow[lane];
        float4 v1 = vrow[lane + 32];
        float4 v2 = vrow[lane + 64];
        acc0.x += w * v0.x; acc0.y += w * v0.y; acc0.z += w * v0.z; acc0.w += w * v0.w;
        acc1.x += w * v1.x; acc1.y += w * v1.y; acc1.z += w * v1.z; acc1.w += w * v1.w;
        acc2.x += w * v2.x; acc2.y += w * v2.y; acc2.z += w * v2.z; acc2.w += w * v2.w;
    }
    *reinterpret_cast<float4*>(&sh_acc[wid][(lane      ) * 4]) = acc0;
    *reinterpret_cast<float4*>(&sh_acc[wid][(lane + 32 ) * 4]) = acc1;
    *reinterpret_cast<float4*>(&sh_acc[wid][(lane + 64 ) * 4]) = acc2;
    __syncthreads();

    // ---- reduce 8 warps' accumulators, write split partial ----
    float* gp = g_partial + (size_t)blk * C_SZ;
    for (int c = tid; c < C_SZ; c += NTHREADS) {
        float t = 0.f;
#pragma unroll
        for (int i = 0; i < NWARPS; i++) t += sh_acc[i][c];
        gp[c] = t;
    }
}

__global__ __launch_bounds__(C_SZ) void attn_combine_kernel(float* __restrict__ out)
{
    const int b = blockIdx.x;
    const int c = threadIdx.x; // 384 threads

    float m = -1e30f;
#pragma unroll
    for (int i = 0; i < SPLITS; i++) m = fmaxf(m, g_m[b * SPLITS + i]);

    float denom = 0.f, val = 0.f;
#pragma unroll
    for (int i = 0; i < SPLITS; i++) {
        const int idx = b * SPLITS + i;
        const float sc = __expf(g_m[idx] - m);
        denom += g_s[idx] * sc;
        val += g_partial[(size_t)idx * C_SZ + c] * sc;
    }
    out[b * C_SZ + c] = val / denom;
}

extern "C" void kernel_launch(void* const* d_in, const int* in_sizes, int n_in,
                              void* d_out, int out_size)
{
    const float* q  = (const float*)d_in[0];
    const float* kc = (const float*)d_in[1];
    const float* v  = (const float*)d_in[2];
    float* out = (float*)d_out;

    attn_split_kernel<<<B_SZ * SPLITS, NTHREADS>>>(q, kc, v);
    attn_combine_kernel<<<B_SZ, C_SZ>>>(out);
}

// round 3
// speedup vs baseline: 1.2774x; 1.2774x over previous
#include <cuda_runtime.h>
#include <cuda_bf16.h>

// Problem constants
#define B_SZ 128
#define L_SZ 4096
#define C_SZ 384
#define SPLITS 8
#define CHUNK (L_SZ / SPLITS)   // 512
#define NTHREADS 256            // 8 warps
#define NWARPS 8

__device__ __align__(16) float g_partial[B_SZ * SPLITS * C_SZ]; // unnormalized sum of w*v
__device__ float g_m[B_SZ * SPLITS];              // split max logit
__device__ float g_s[B_SZ * SPLITS];              // split sum exp

__global__ __launch_bounds__(NTHREADS) void attn_split_kernel(
    const float* __restrict__ q,
    const float* __restrict__ kc,
    const float* __restrict__ v)
{
    const int blk  = blockIdx.x;        // 0 .. B*SPLITS-1
    const int b    = blk / SPLITS;
    const int s    = blk % SPLITS;
    const int l0   = s * CHUNK;
    const int tid  = threadIdx.x;
    const int wid  = tid >> 5;
    const int lane = tid & 31;

    __shared__ __align__(16) float sh_q[C_SZ];
    __shared__ float sh_m[NWARPS];
    __shared__ float sh_s[NWARPS];
    __shared__ __align__(16) float sh_acc[NWARPS][C_SZ]; // 12 KB

    // load q row into shared
    for (int i = tid; i < C_SZ; i += NTHREADS) sh_q[i] = q[b * C_SZ + i];
    __syncthreads();

    // each lane's 3 float4 fragments of q (covers 384 floats per warp)
    float4 qf[3];
#pragma unroll
    for (int j = 0; j < 3; j++)
        qf[j] = *reinterpret_cast<const float4*>(&sh_q[(lane + 32 * j) * 4]);

    const float inv_T = 1.0f / 19.595917942265423f;
    const float* kbase = kc + ((size_t)b * L_SZ + l0) * C_SZ;
    const float* vbase = v  + ((size_t)b * L_SZ + l0) * C_SZ;

    // ---- Single pass: online softmax, 2 rows per warp per iteration ----
    float m = -1e30f, ssum = 0.f;
    float4 a0 = {0,0,0,0}, a1 = {0,0,0,0}, a2 = {0,0,0,0};

    for (int l = wid * 2; l < CHUNK; l += NWARPS * 2) {
        const float4* k0 = reinterpret_cast<const float4*>(kbase + (size_t)l * C_SZ);
        const float4* k1 = reinterpret_cast<const float4*>(kbase + (size_t)(l + 1) * C_SZ);
        const float4* v0 = reinterpret_cast<const float4*>(vbase + (size_t)l * C_SZ);
        const float4* v1 = reinterpret_cast<const float4*>(vbase + (size_t)(l + 1) * C_SZ);

        // issue all 12 loads up front for max MLP
        float4 kk0_0 = k0[lane], kk0_1 = k0[lane + 32], kk0_2 = k0[lane + 64];
        float4 kk1_0 = k1[lane], kk1_1 = k1[lane + 32], kk1_2 = k1[lane + 64];
        float4 vv0_0 = v0[lane], vv0_1 = v0[lane + 32], vv0_2 = v0[lane + 64];
        float4 vv1_0 = v1[lane], vv1_1 = v1[lane + 32], vv1_2 = v1[lane + 64];

        float d0 = qf[0].x*kk0_0.x + qf[0].y*kk0_0.y + qf[0].z*kk0_0.z + qf[0].w*kk0_0.w
                 + qf[1].x*kk0_1.x + qf[1].y*kk0_1.y + qf[1].z*kk0_1.z + qf[1].w*kk0_1.w
                 + qf[2].x*kk0_2.x + qf[2].y*kk0_2.y + qf[2].z*kk0_2.z + qf[2].w*kk0_2.w;
        float d1 = qf[0].x*kk1_0.x + qf[0].y*kk1_0.y + qf[0].z*kk1_0.z + qf[0].w*kk1_0.w
                 + qf[1].x*kk1_1.x + qf[1].y*kk1_1.y + qf[1].z*kk1_1.z + qf[1].w*kk1_1.w
                 + qf[2].x*kk1_2.x + qf[2].y*kk1_2.y + qf[2].z*kk1_2.z + qf[2].w*kk1_2.w;

#pragma unroll
        for (int o = 16; o; o >>= 1) {
            d0 += __shfl_xor_sync(0xffffffffu, d0, o);
            d1 += __shfl_xor_sync(0xffffffffu, d1, o);
        }
        d0 *= inv_T;
        d1 *= inv_T;

        const float mn   = fmaxf(m, fmaxf(d0, d1));
        const float corr = __expf(m - mn);
        const float w0   = __expf(d0 - mn);
        const float w1   = __expf(d1 - mn);
        m = mn;
        ssum = ssum * corr + w0 + w1;

        a0.x = a0.x*corr + w0*vv0_0.x + w1*vv1_0.x;
        a0.y = a0.y*corr + w0*vv0_0.y + w1*vv1_0.y;
        a0.z = a0.z*corr + w0*vv0_0.z + w1*vv1_0.z;
        a0.w = a0.w*corr + w0*vv0_0.w + w1*vv1_0.w;
        a1.x = a1.x*corr + w0*vv0_1.x + w1*vv1_1.x;
        a1.y = a1.y*corr + w0*vv0_1.y + w1*vv1_1.y;
        a1.z = a1.z*corr + w0*vv0_1.z + w1*vv1_1.z;
        a1.w = a1.w*corr + w0*vv0_1.w + w1*vv1_1.w;
        a2.x = a2.x*corr + w0*vv0_2.x + w1*vv1_2.x;
        a2.y = a2.y*corr + w0*vv0_2.y + w1*vv1_2.y;
        a2.z = a2.z*corr + w0*vv0_2.z + w1*vv1_2.z;
        a2.w = a2.w*corr + w0*vv0_2.w + w1*vv1_2.w;
    }

    // ---- merge 8 warps' online-softmax states ----
    if (lane == 0) { sh_m[wid] = m; sh_s[wid] = ssum; }
    __syncthreads();

    float mB = sh_m[0];
#pragma unroll
    for (int i = 1; i < NWARPS; i++) mB = fmaxf(mB, sh_m[i]);

    // scale this warp's accumulator into the block frame, stash in shared
    const float cw = __expf(m - mB);
    a0.x *= cw; a0.y *= cw; a0.z *= cw; a0.w *= cw;
    a1.x *= cw; a1.y *= cw; a1.z *= cw; a1.w *= cw;
    a2.x *= cw; a2.y *= cw; a2.z *= cw; a2.w *= cw;
    *reinterpret_cast<float4*>(&sh_acc[wid][(lane     ) * 4]) = a0;
    *reinterpret_cast<float4*>(&sh_acc[wid][(lane + 32) * 4]) = a1;
    *reinterpret_cast<float4*>(&sh_acc[wid][(lane + 64) * 4]) = a2;
    __syncthreads();

    if (tid == 0) {
        float t = 0.f;
#pragma unroll
        for (int i = 0; i < NWARPS; i++) t += sh_s[i] * __expf(sh_m[i] - mB);
        g_m[blk] = mB;
        g_s[blk] = t;
    }

    // reduce 8 warps' accumulators, write split partial
    float* gp = g_partial + (size_t)blk * C_SZ;
    for (int c = tid; c < C_SZ; c += NTHREADS) {
        float t = 0.f;
#pragma unroll
        for (int i = 0; i < NWARPS; i++) t += sh_acc[i][c];
        gp[c] = t;
    }
}

__global__ __launch_bounds__(C_SZ) void attn_combine_kernel(float* __restrict__ out)
{
    const int b = blockIdx.x;
    const int c = threadIdx.x; // 384 threads

    float m = -1e30f;
#pragma unroll
    for (int i = 0; i < SPLITS; i++) m = fmaxf(m, g_m[b * SPLITS + i]);

    float denom = 0.f, val = 0.f;
#pragma unroll
    for (int i = 0; i < SPLITS; i++) {
        const int idx = b * SPLITS + i;
        const float sc = __expf(g_m[idx] - m);
        denom += g_s[idx] * sc;
        val += g_partial[(size_t)idx * C_SZ + c] * sc;
    }
    out[b * C_SZ + c] = val / denom;
}

extern "C" void kernel_launch(void* const* d_in, const int* in_sizes, int n_in,
                              void* d_out, int out_size)
{
    const float* q  = (const float*)d_in[0];
    const float* kc = (const float*)d_in[1];
    const float* v  = (const float*)d_in[2];
    float* out = (float*)d_out;

    attn_split_kernel<<<B_SZ * SPLITS, NTHREADS>>>(q, kc, v);
    attn_combine_kernel<<<B_SZ, C_SZ>>>(out);
}